// round 1
// baseline (speedup 1.0000x reference)
#include <cuda_runtime.h>
#include <cuda_bf16.h>
#include <math.h>

// Problem constants
#define Bn   2
#define Sn   2048
#define Dn   1024
#define Hn   16
#define DHn  64
#define Mn   (Bn*Sn)          // 4096 rows
#define DFF  (4*Dn)           // 4096
#define DG   (2*Dn)           // 2048
#define EPSV 1e-5f

// -------------------- scratch (device globals; no allocation) --------------------
__device__ float g_xn1 [Mn*Dn];
__device__ float g_q   [Mn*Dn];
__device__ float g_k   [Mn*Dn];
__device__ float g_v   [Mn*Dn];
__device__ float g_attn[Mn*Dn];
__device__ float g_x1  [Mn*Dn];
__device__ float g_xn2 [Mn*Dn];
__device__ float g_h   [Mn*DFF];
__device__ float g_glu [Mn*DG];

// ==================== LayerNorm: one block per row of 1024 ====================
__global__ __launch_bounds__(256) void ln_kernel(const float* __restrict__ x,
                                                 const float* __restrict__ gamma,
                                                 const float* __restrict__ beta,
                                                 float* __restrict__ out) {
    const int row = blockIdx.x;
    const int tid = threadIdx.x;
    const float4* xr = (const float4*)(x + (size_t)row * Dn);
    float4 v = xr[tid];                       // 256 threads * 4 = 1024
    float s  = v.x + v.y + v.z + v.w;
    float ss = v.x*v.x + v.y*v.y + v.z*v.z + v.w*v.w;
    // warp reduce
    #pragma unroll
    for (int off = 16; off > 0; off >>= 1) {
        s  += __shfl_xor_sync(0xffffffffu, s,  off);
        ss += __shfl_xor_sync(0xffffffffu, ss, off);
    }
    __shared__ float red[2][8];
    const int wid = tid >> 5, lid = tid & 31;
    if (lid == 0) { red[0][wid] = s; red[1][wid] = ss; }
    __syncthreads();
    __shared__ float smu, srstd;
    if (tid == 0) {
        float ts = 0.f, tss = 0.f;
        #pragma unroll
        for (int i = 0; i < 8; ++i) { ts += red[0][i]; tss += red[1][i]; }
        float mu  = ts * (1.0f / Dn);
        float var = tss * (1.0f / Dn) - mu * mu;
        smu = mu; srstd = rsqrtf(var + EPSV);
    }
    __syncthreads();
    const float mu = smu, rstd = srstd;
    float4 g = ((const float4*)gamma)[tid];
    float4 b = ((const float4*)beta)[tid];
    float4 o;
    o.x = g.x * (v.x - mu) * rstd + b.x;
    o.y = g.y * (v.y - mu) * rstd + b.y;
    o.z = g.z * (v.z - mu) * rstd + b.z;
    o.w = g.w * (v.w - mu) * rstd + b.w;
    ((float4*)(out + (size_t)row * Dn))[tid] = o;
}

// ==================== SGEMM: C[M,N] = A[M,K] @ B[K,N] (+ R) ====================
#define BM 128
#define BN 128
#define BK 16

template<bool RESID>
__global__ __launch_bounds__(256) void sgemm_kernel(
    const float* __restrict__ A, const float* __restrict__ Bm,
    const float* __restrict__ R, float* __restrict__ C,
    int M_, int N_, int K_) {
    __shared__ float As[2][BK][BM + 4];
    __shared__ float Bs[2][BK][BN + 4];

    const int tid = threadIdx.x;
    const int bx = blockIdx.x, by = blockIdx.y;
    const int ty = tid >> 4, tx = tid & 15;

    float acc[8][8];
    #pragma unroll
    for (int i = 0; i < 8; ++i)
        #pragma unroll
        for (int j = 0; j < 8; ++j) acc[i][j] = 0.f;

    float4 ra[2], rb[2];
    // index precompute for loads
    const int a_row0 = (tid + 0)   >> 2, a_c40 = (tid + 0)   & 3;
    const int a_row1 = (tid + 256) >> 2, a_c41 = (tid + 256) & 3;
    const int b_row0 = (tid + 0)   >> 5, b_c40 = (tid + 0)   & 31;
    const int b_row1 = (tid + 256) >> 5, b_c41 = (tid + 256) & 31;

    const int nt = K_ / BK;

    auto fetch = [&](int kt) {
        ra[0] = *(const float4*)&A[(size_t)(by*BM + a_row0)*K_ + kt*BK + a_c40*4];
        ra[1] = *(const float4*)&A[(size_t)(by*BM + a_row1)*K_ + kt*BK + a_c41*4];
        rb[0] = *(const float4*)&Bm[(size_t)(kt*BK + b_row0)*N_ + bx*BN + b_c40*4];
        rb[1] = *(const float4*)&Bm[(size_t)(kt*BK + b_row1)*N_ + bx*BN + b_c41*4];
    };
    auto store = [&](int buf) {
        As[buf][a_c40*4+0][a_row0] = ra[0].x;
        As[buf][a_c40*4+1][a_row0] = ra[0].y;
        As[buf][a_c40*4+2][a_row0] = ra[0].z;
        As[buf][a_c40*4+3][a_row0] = ra[0].w;
        As[buf][a_c41*4+0][a_row1] = ra[1].x;
        As[buf][a_c41*4+1][a_row1] = ra[1].y;
        As[buf][a_c41*4+2][a_row1] = ra[1].z;
        As[buf][a_c41*4+3][a_row1] = ra[1].w;
        *(float4*)&Bs[buf][b_row0][b_c40*4] = rb[0];
        *(float4*)&Bs[buf][b_row1][b_c41*4] = rb[1];
    };

    fetch(0); store(0);
    __syncthreads();

    for (int kt = 0; kt < nt; ++kt) {
        const int buf = kt & 1;
        if (kt + 1 < nt) fetch(kt + 1);
        #pragma unroll
        for (int kk = 0; kk < BK; ++kk) {
            float a[8], b[8];
            *(float4*)&a[0] = *(float4*)&As[buf][kk][ty*8];
            *(float4*)&a[4] = *(float4*)&As[buf][kk][ty*8 + 4];
            *(float4*)&b[0] = *(float4*)&Bs[buf][kk][tx*8];
            *(float4*)&b[4] = *(float4*)&Bs[buf][kk][tx*8 + 4];
            #pragma unroll
            for (int i = 0; i < 8; ++i)
                #pragma unroll
                for (int j = 0; j < 8; ++j)
                    acc[i][j] = fmaf(a[i], b[j], acc[i][j]);
        }
        if (kt + 1 < nt) { store((kt + 1) & 1); __syncthreads(); }
    }

    // epilogue
    #pragma unroll
    for (int i = 0; i < 8; ++i) {
        const int row = by*BM + ty*8 + i;
        #pragma unroll
        for (int j4 = 0; j4 < 2; ++j4) {
            const int col = bx*BN + tx*8 + j4*4;
            float4 t;
            t.x = acc[i][j4*4+0]; t.y = acc[i][j4*4+1];
            t.z = acc[i][j4*4+2]; t.w = acc[i][j4*4+3];
            if (RESID) {
                float4 r = *(const float4*)&R[(size_t)row*N_ + col];
                t.x += r.x; t.y += r.y; t.z += r.z; t.w += r.w;
            }
            *(float4*)&C[(size_t)row*N_ + col] = t;
        }
    }
}

// ==================== GLU: glu = left * sigmoid(right) ====================
__global__ __launch_bounds__(256) void glu_kernel(const float* __restrict__ h,
                                                  float* __restrict__ g) {
    const int idx = blockIdx.x * blockDim.x + threadIdx.x;   // over Mn*DG/4
    const int row = idx >> 9;        // DG/4 = 512
    const int c4  = idx & 511;
    float4 l = *(const float4*)&h[(size_t)row*DFF + c4*4];
    float4 r = *(const float4*)&h[(size_t)row*DFF + DG + c4*4];
    float4 o;
    o.x = l.x / (1.f + expf(-r.x));
    o.y = l.y / (1.f + expf(-r.y));
    o.z = l.z / (1.f + expf(-r.z));
    o.w = l.w / (1.f + expf(-r.w));
    *(float4*)&g[(size_t)row*DG + c4*4] = o;
}

// ==================== causal flash attention, 64x64 tiles ====================
// grid: (S/64, H, B), block 256.  smem: Qs,Ks,Vs,Ps each 64x68 f32.
#define ATTN_SMEM (4 * 64 * 68 * 4)

__global__ __launch_bounds__(256) void attn_kernel(
    const float* __restrict__ Q, const float* __restrict__ K,
    const float* __restrict__ V, const int* __restrict__ mask,
    float* __restrict__ O) {
    extern __shared__ float sm[];
    float* Qs = sm;
    float* Ks = sm + 64*68;
    float* Vs = sm + 2*64*68;
    float* Ps = sm + 3*64*68;
    __shared__ int msk[64];

    const int qt = blockIdx.x, h = blockIdx.y, b = blockIdx.z;
    const int tid = threadIdx.x;
    const int r  = tid >> 2;            // row 0..63
    const int cb = (tid & 3) << 4;      // col base 0/16/32/48
    const int qg = qt*64 + r;

    // load Q tile
    for (int i = tid; i < 1024; i += 256) {
        const int rr = i >> 4, c4 = i & 15;
        *(float4*)&Qs[rr*68 + c4*4] =
            *(const float4*)&Q[(size_t)(b*Sn + qt*64 + rr)*Dn + h*DHn + c4*4];
    }

    float mrun = -INFINITY, lrun = 0.f;
    float o[16];
    #pragma unroll
    for (int c = 0; c < 16; ++c) o[c] = 0.f;
    const float scale = 0.125f;  // 1/sqrt(64)

    for (int kt = 0; kt <= qt; ++kt) {
        __syncthreads();  // protect Ks/Vs/Ps from previous-iteration readers
        for (int i = tid; i < 1024; i += 256) {
            const int rr = i >> 4, c4 = i & 15;
            const size_t gofs = (size_t)(b*Sn + kt*64 + rr)*Dn + h*DHn + c4*4;
            *(float4*)&Ks[rr*68 + c4*4] = *(const float4*)&K[gofs];
            *(float4*)&Vs[rr*68 + c4*4] = *(const float4*)&V[gofs];
        }
        if (tid < 64) msk[tid] = mask[b*Sn + kt*64 + tid];
        __syncthreads();

        // scores: s[j] = Q[r,:] . K[cb+j,:]
        float s[16];
        #pragma unroll
        for (int j = 0; j < 16; ++j) s[j] = 0.f;
        #pragma unroll 4
        for (int d4 = 0; d4 < 16; ++d4) {
            const float4 qv = *(const float4*)&Qs[r*68 + d4*4];
            #pragma unroll
            for (int j = 0; j < 16; ++j) {
                const float4 kv = *(const float4*)&Ks[(cb+j)*68 + d4*4];
                s[j] += qv.x*kv.x + qv.y*kv.y + qv.z*kv.z + qv.w*kv.w;
            }
        }
        // mask + scale
        #pragma unroll
        for (int j = 0; j < 16; ++j) {
            const int kg = kt*64 + cb + j;
            const bool ok = (kg <= qg) && (msk[cb + j] != 0);
            s[j] = ok ? s[j] * scale : -INFINITY;
        }
        // online softmax update (4 threads per row share state via shfl)
        float mloc = s[0];
        #pragma unroll
        for (int j = 1; j < 16; ++j) mloc = fmaxf(mloc, s[j]);
        mloc = fmaxf(mloc, __shfl_xor_sync(0xffffffffu, mloc, 1));
        mloc = fmaxf(mloc, __shfl_xor_sync(0xffffffffu, mloc, 2));
        const float mnew = fmaxf(mrun, mloc);
        const float alpha = expf(mrun - mnew);
        float p[16], psum = 0.f;
        #pragma unroll
        for (int j = 0; j < 16; ++j) { p[j] = expf(s[j] - mnew); psum += p[j]; }
        psum += __shfl_xor_sync(0xffffffffu, psum, 1);
        psum += __shfl_xor_sync(0xffffffffu, psum, 2);
        lrun = lrun * alpha + psum;
        mrun = mnew;
        #pragma unroll
        for (int c = 0; c < 16; ++c) o[c] *= alpha;
        #pragma unroll
        for (int j = 0; j < 16; ++j) Ps[r*68 + cb + j] = p[j];
        __syncthreads();
        // O += P @ V  (each thread: its 16 output columns, all 64 kv rows)
        #pragma unroll 4
        for (int j = 0; j < 64; ++j) {
            const float pv = Ps[r*68 + j];
            #pragma unroll
            for (int c4 = 0; c4 < 4; ++c4) {
                const float4 vv = *(const float4*)&Vs[j*68 + cb + c4*4];
                o[c4*4+0] += pv * vv.x;
                o[c4*4+1] += pv * vv.y;
                o[c4*4+2] += pv * vv.z;
                o[c4*4+3] += pv * vv.w;
            }
        }
    }

    const float inv = 1.f / lrun;
    #pragma unroll
    for (int c4 = 0; c4 < 4; ++c4) {
        float4 t;
        t.x = o[c4*4+0] * inv; t.y = o[c4*4+1] * inv;
        t.z = o[c4*4+2] * inv; t.w = o[c4*4+3] * inv;
        *(float4*)&O[(size_t)(b*Sn + qt*64 + r)*Dn + h*DHn + cb + c4*4] = t;
    }
}

// ==================== launch ====================
extern "C" void kernel_launch(void* const* d_in, const int* in_sizes, int n_in,
                              void* d_out, int out_size) {
    const float* x     = (const float*)d_in[0];
    const int*   amask = (const int*)  d_in[1];
    const float* Wq    = (const float*)d_in[2];
    const float* Wk    = (const float*)d_in[3];
    const float* Wv    = (const float*)d_in[4];
    const float* Wo    = (const float*)d_in[5];
    const float* W1    = (const float*)d_in[6];
    const float* W2    = (const float*)d_in[7];
    const float* gamma1= (const float*)d_in[8];
    const float* beta1 = (const float*)d_in[9];
    const float* gamma2= (const float*)d_in[10];
    const float* beta2 = (const float*)d_in[11];
    float* out = (float*)d_out;

    float *xn1, *q, *k, *v, *attn, *x1, *xn2, *hbuf, *glu;
    cudaGetSymbolAddress((void**)&xn1,  g_xn1);
    cudaGetSymbolAddress((void**)&q,    g_q);
    cudaGetSymbolAddress((void**)&k,    g_k);
    cudaGetSymbolAddress((void**)&v,    g_v);
    cudaGetSymbolAddress((void**)&attn, g_attn);
    cudaGetSymbolAddress((void**)&x1,   g_x1);
    cudaGetSymbolAddress((void**)&xn2,  g_xn2);
    cudaGetSymbolAddress((void**)&hbuf, g_h);
    cudaGetSymbolAddress((void**)&glu,  g_glu);

    cudaFuncSetAttribute(attn_kernel, cudaFuncAttributeMaxDynamicSharedMemorySize, ATTN_SMEM);

    // 1. LN1
    ln_kernel<<<Mn, 256>>>(x, gamma1, beta1, xn1);

    // 2. Q,K,V projections
    dim3 gD(Dn/BN, Mn/BM);
    sgemm_kernel<false><<<gD, 256>>>(xn1, Wq, nullptr, q, Mn, Dn, Dn);
    sgemm_kernel<false><<<gD, 256>>>(xn1, Wk, nullptr, k, Mn, Dn, Dn);
    sgemm_kernel<false><<<gD, 256>>>(xn1, Wv, nullptr, v, Mn, Dn, Dn);

    // 3. causal attention
    dim3 gA(Sn/64, Hn, Bn);
    attn_kernel<<<gA, 256, ATTN_SMEM>>>(q, k, v, amask, attn);

    // 4. output projection + residual
    sgemm_kernel<true><<<gD, 256>>>(attn, Wo, x, x1, Mn, Dn, Dn);

    // 5. LN2
    ln_kernel<<<Mn, 256>>>(x1, gamma2, beta2, xn2);

    // 6. W1 (N=4096)
    dim3 gF(DFF/BN, Mn/BM);
    sgemm_kernel<false><<<gF, 256>>>(xn2, W1, nullptr, hbuf, Mn, DFF, Dn);

    // 7. GLU
    glu_kernel<<<(Mn*DG/4)/256, 256>>>(hbuf, glu);

    // 8. W2 + residual -> out
    sgemm_kernel<true><<<gD, 256>>>(glu, W2, x1, out, Mn, Dn, DG);
}

// round 2
// speedup vs baseline: 8.5363x; 8.5363x over previous
#include <cuda_runtime.h>
#include <cuda_bf16.h>
#include <math.h>
#include <stdint.h>

// Problem constants
#define Bn   2
#define Sn   2048
#define Dn   1024
#define Hn   16
#define DHn  64
#define Mn   (Bn*Sn)          // 4096 rows
#define DFF  (4*Dn)           // 4096
#define DG   (2*Dn)           // 2048
#define EPSV 1e-5f

// -------------------- scratch (device globals; no allocation) --------------------
__device__ float g_xn1 [Mn*Dn];
__device__ float g_q   [Mn*Dn];
__device__ float g_k   [Mn*Dn];
__device__ float g_v   [Mn*Dn];
__device__ float g_attn[Mn*Dn];
__device__ float g_x1  [Mn*Dn];
__device__ float g_xn2 [Mn*Dn];
__device__ float g_h   [Mn*DFF];
__device__ float g_glu [Mn*DG];

// -------------------- tf32 helpers --------------------
__device__ __forceinline__ uint32_t f2tf(float f) {
    uint32_t r;
    asm("cvt.rna.tf32.f32 %0, %1;" : "=r"(r) : "f"(f));
    return r;
}

__device__ __forceinline__ void mma_tf32(float c[4], const uint32_t a[4],
                                         uint32_t b0, uint32_t b1) {
    asm volatile(
        "mma.sync.aligned.m16n8k8.row.col.f32.tf32.tf32.f32 "
        "{%0,%1,%2,%3}, {%4,%5,%6,%7}, {%8,%9}, {%0,%1,%2,%3};"
        : "+f"(c[0]), "+f"(c[1]), "+f"(c[2]), "+f"(c[3])
        : "r"(a[0]), "r"(a[1]), "r"(a[2]), "r"(a[3]), "r"(b0), "r"(b1));
}

// ==================== LayerNorm ====================
__global__ __launch_bounds__(256) void ln_kernel(const float* __restrict__ x,
                                                 const float* __restrict__ gamma,
                                                 const float* __restrict__ beta,
                                                 float* __restrict__ out) {
    const int row = blockIdx.x;
    const int tid = threadIdx.x;
    const float4* xr = (const float4*)(x + (size_t)row * Dn);
    float4 v = xr[tid];
    float s  = v.x + v.y + v.z + v.w;
    float ss = v.x*v.x + v.y*v.y + v.z*v.z + v.w*v.w;
    #pragma unroll
    for (int off = 16; off > 0; off >>= 1) {
        s  += __shfl_xor_sync(0xffffffffu, s,  off);
        ss += __shfl_xor_sync(0xffffffffu, ss, off);
    }
    __shared__ float red[2][8];
    const int wid = tid >> 5, lid = tid & 31;
    if (lid == 0) { red[0][wid] = s; red[1][wid] = ss; }
    __syncthreads();
    __shared__ float smu, srstd;
    if (tid == 0) {
        float ts = 0.f, tss = 0.f;
        #pragma unroll
        for (int i = 0; i < 8; ++i) { ts += red[0][i]; tss += red[1][i]; }
        float mu  = ts * (1.0f / Dn);
        float var = tss * (1.0f / Dn) - mu * mu;
        smu = mu; srstd = rsqrtf(var + EPSV);
    }
    __syncthreads();
    const float mu = smu, rstd = srstd;
    float4 g = ((const float4*)gamma)[tid];
    float4 b = ((const float4*)beta)[tid];
    float4 o;
    o.x = g.x * (v.x - mu) * rstd + b.x;
    o.y = g.y * (v.y - mu) * rstd + b.y;
    o.z = g.z * (v.z - mu) * rstd + b.z;
    o.w = g.w * (v.w - mu) * rstd + b.w;
    ((float4*)(out + (size_t)row * Dn))[tid] = o;
}

// ==================== TF32 tensor-core GEMM: C = A @ B (+ R) ====================
#define BM 128
#define BN 128
#define BK 16

template<bool RESID>
__global__ __launch_bounds__(256) void gemm_tf32(
    const float* __restrict__ A, const float* __restrict__ Bm,
    const float* __restrict__ R, float* __restrict__ C,
    int M_, int N_, int K_) {
    __shared__ uint32_t As[2][BK][BM + 4];   // [k][m], pad 4 => conflict-free frags
    __shared__ uint32_t Bs[2][BK][BN + 4];   // [k][n]

    const int tid = threadIdx.x;
    const int bx = blockIdx.x, by = blockIdx.y;
    const int wid = tid >> 5, lane = tid & 31;
    const int g = lane >> 2, t = lane & 3;       // group / thread-in-group
    const int wr = wid >> 2, wc = wid & 3;       // warp grid 2x4
    const int wm = wr * 64, wn = wc * 32;        // warp tile 64x32

    float acc[4][4][4];
    #pragma unroll
    for (int i = 0; i < 4; ++i)
        #pragma unroll
        for (int j = 0; j < 4; ++j)
            #pragma unroll
            for (int e = 0; e < 4; ++e) acc[i][j][e] = 0.f;

    float4 ra[2], rb[2];
    const int a_row0 = (tid + 0)   >> 2, a_c40 = (tid + 0)   & 3;
    const int a_row1 = (tid + 256) >> 2, a_c41 = (tid + 256) & 3;
    const int b_row0 = (tid + 0)   >> 5, b_c40 = (tid + 0)   & 31;
    const int b_row1 = (tid + 256) >> 5, b_c41 = (tid + 256) & 31;

    const int nt = K_ / BK;

    auto fetch = [&](int kt) {
        ra[0] = *(const float4*)&A[(size_t)(by*BM + a_row0)*K_ + kt*BK + a_c40*4];
        ra[1] = *(const float4*)&A[(size_t)(by*BM + a_row1)*K_ + kt*BK + a_c41*4];
        rb[0] = *(const float4*)&Bm[(size_t)(kt*BK + b_row0)*N_ + bx*BN + b_c40*4];
        rb[1] = *(const float4*)&Bm[(size_t)(kt*BK + b_row1)*N_ + bx*BN + b_c41*4];
    };
    auto store = [&](int buf) {
        As[buf][a_c40*4+0][a_row0] = f2tf(ra[0].x);
        As[buf][a_c40*4+1][a_row0] = f2tf(ra[0].y);
        As[buf][a_c40*4+2][a_row0] = f2tf(ra[0].z);
        As[buf][a_c40*4+3][a_row0] = f2tf(ra[0].w);
        As[buf][a_c41*4+0][a_row1] = f2tf(ra[1].x);
        As[buf][a_c41*4+1][a_row1] = f2tf(ra[1].y);
        As[buf][a_c41*4+2][a_row1] = f2tf(ra[1].z);
        As[buf][a_c41*4+3][a_row1] = f2tf(ra[1].w);
        uint4 u0 = { f2tf(rb[0].x), f2tf(rb[0].y), f2tf(rb[0].z), f2tf(rb[0].w) };
        uint4 u1 = { f2tf(rb[1].x), f2tf(rb[1].y), f2tf(rb[1].z), f2tf(rb[1].w) };
        *(uint4*)&Bs[buf][b_row0][b_c40*4] = u0;
        *(uint4*)&Bs[buf][b_row1][b_c41*4] = u1;
    };

    fetch(0); store(0);
    __syncthreads();

    for (int kt = 0; kt < nt; ++kt) {
        const int buf = kt & 1;
        if (kt + 1 < nt) fetch(kt + 1);
        #pragma unroll
        for (int kk = 0; kk < 2; ++kk) {
            const int k0 = kk * 8;
            uint32_t afr[4][4], bfr[4][2];
            #pragma unroll
            for (int i = 0; i < 4; ++i) {
                afr[i][0] = As[buf][k0 + t    ][wm + i*16 + g    ];
                afr[i][1] = As[buf][k0 + t    ][wm + i*16 + g + 8];
                afr[i][2] = As[buf][k0 + t + 4][wm + i*16 + g    ];
                afr[i][3] = As[buf][k0 + t + 4][wm + i*16 + g + 8];
            }
            #pragma unroll
            for (int j = 0; j < 4; ++j) {
                bfr[j][0] = Bs[buf][k0 + t    ][wn + j*8 + g];
                bfr[j][1] = Bs[buf][k0 + t + 4][wn + j*8 + g];
            }
            #pragma unroll
            for (int i = 0; i < 4; ++i)
                #pragma unroll
                for (int j = 0; j < 4; ++j)
                    mma_tf32(acc[i][j], afr[i], bfr[j][0], bfr[j][1]);
        }
        if (kt + 1 < nt) { store((kt + 1) & 1); __syncthreads(); }
    }

    // epilogue (C fragment: rows g,g+8; cols 2t,2t+1 within each 16x8 tile)
    #pragma unroll
    for (int i = 0; i < 4; ++i) {
        const int row0 = by*BM + wm + i*16 + g;
        const int row1 = row0 + 8;
        #pragma unroll
        for (int j = 0; j < 4; ++j) {
            const int col = bx*BN + wn + j*8 + t*2;
            float2 v0 = { acc[i][j][0], acc[i][j][1] };
            float2 v1 = { acc[i][j][2], acc[i][j][3] };
            if (RESID) {
                float2 r0 = *(const float2*)&R[(size_t)row0*N_ + col];
                float2 r1 = *(const float2*)&R[(size_t)row1*N_ + col];
                v0.x += r0.x; v0.y += r0.y;
                v1.x += r1.x; v1.y += r1.y;
            }
            *(float2*)&C[(size_t)row0*N_ + col] = v0;
            *(float2*)&C[(size_t)row1*N_ + col] = v1;
        }
    }
}

// ==================== GLU ====================
__global__ __launch_bounds__(256) void glu_kernel(const float* __restrict__ h,
                                                  float* __restrict__ g) {
    const int idx = blockIdx.x * blockDim.x + threadIdx.x;
    const int row = idx >> 9;
    const int c4  = idx & 511;
    float4 l = *(const float4*)&h[(size_t)row*DFF + c4*4];
    float4 r = *(const float4*)&h[(size_t)row*DFF + DG + c4*4];
    float4 o;
    o.x = l.x / (1.f + expf(-r.x));
    o.y = l.y / (1.f + expf(-r.y));
    o.z = l.z / (1.f + expf(-r.z));
    o.w = l.w / (1.f + expf(-r.w));
    *(float4*)&g[(size_t)row*DG + c4*4] = o;
}

// ==================== causal flash attention (tf32 tensor cores) ====================
// grid: (S/64, H, B), block 128 (4 warps). Warp w owns q rows [w*16, w*16+16).
// smem: Ks[64][68], Vs[64][68], Ps[64][68] (all tf32 bit patterns)
#define APAD 68
#define ATTN_SMEM (3 * 64 * APAD * 4)

__global__ __launch_bounds__(128) void attn_tf32(
    const float* __restrict__ Q, const float* __restrict__ K,
    const float* __restrict__ V, const int* __restrict__ mask,
    float* __restrict__ O) {
    extern __shared__ uint32_t sm_u[];
    uint32_t* Ks = sm_u;
    uint32_t* Vs = sm_u + 64*APAD;
    uint32_t* Ps = sm_u + 2*64*APAD;
    __shared__ int msk[64];

    const int qt = blockIdx.x, h = blockIdx.y, b = blockIdx.z;
    const int tid = threadIdx.x;
    const int wid = tid >> 5, lane = tid & 31;
    const int g = lane >> 2, t = lane & 3;

    // Q fragments held in registers for the whole block of kv tiles
    const float* Qb = Q + ((size_t)(b*Sn + qt*64 + wid*16))*Dn + h*DHn;
    uint32_t qa[8][4];
    #pragma unroll
    for (int ks = 0; ks < 8; ++ks) {
        qa[ks][0] = f2tf(Qb[(size_t)(g    )*Dn + ks*8 + t    ]);
        qa[ks][1] = f2tf(Qb[(size_t)(g + 8)*Dn + ks*8 + t    ]);
        qa[ks][2] = f2tf(Qb[(size_t)(g    )*Dn + ks*8 + t + 4]);
        qa[ks][3] = f2tf(Qb[(size_t)(g + 8)*Dn + ks*8 + t + 4]);
    }

    float o[8][4];
    #pragma unroll
    for (int j = 0; j < 8; ++j)
        #pragma unroll
        for (int e = 0; e < 4; ++e) o[j][e] = 0.f;
    float m0 = -1e30f, m1 = -1e30f, l0 = 0.f, l1 = 0.f;
    const float scale = 0.125f;       // 1/sqrt(64)

    const int rowg0 = qt*64 + wid*16 + g;
    const int rowg1 = rowg0 + 8;

    for (int kt = 0; kt <= qt; ++kt) {
        __syncthreads();
        // load K,V tiles (cvt to tf32)
        for (int i = tid; i < 1024; i += 128) {
            const int rr = i >> 4, c4 = i & 15;
            const size_t gofs = (size_t)(b*Sn + kt*64 + rr)*Dn + h*DHn + c4*4;
            float4 kf = *(const float4*)&K[gofs];
            float4 vf = *(const float4*)&V[gofs];
            uint4 ku = { f2tf(kf.x), f2tf(kf.y), f2tf(kf.z), f2tf(kf.w) };
            uint4 vu = { f2tf(vf.x), f2tf(vf.y), f2tf(vf.z), f2tf(vf.w) };
            *(uint4*)&Ks[rr*APAD + c4*4] = ku;
            *(uint4*)&Vs[rr*APAD + c4*4] = vu;
        }
        if (tid < 64) msk[tid] = mask[b*Sn + kt*64 + tid];
        __syncthreads();

        // S = Q @ K^T  (16x64 per warp)
        float sc[8][4];
        #pragma unroll
        for (int j = 0; j < 8; ++j)
            #pragma unroll
            for (int e = 0; e < 4; ++e) sc[j][e] = 0.f;
        #pragma unroll
        for (int ks = 0; ks < 8; ++ks) {
            #pragma unroll
            for (int j = 0; j < 8; ++j) {
                uint32_t b0 = Ks[(j*8 + g)*APAD + ks*8 + t    ];
                uint32_t b1 = Ks[(j*8 + g)*APAD + ks*8 + t + 4];
                mma_tf32(sc[j], qa[ks], b0, b1);
            }
        }

        // scale + causal + key mask
        #pragma unroll
        for (int j = 0; j < 8; ++j) {
            #pragma unroll
            for (int e = 0; e < 4; ++e) {
                const int cl  = j*8 + t*2 + (e & 1);
                const int kg  = kt*64 + cl;
                const int row = (e < 2) ? rowg0 : rowg1;
                const bool ok = (kg <= row) && (msk[cl] != 0);
                sc[j][e] = ok ? sc[j][e] * scale : -1e30f;
            }
        }

        // online softmax (per lane: rows g and g+8; stats shared across quad)
        float rm0 = -1e30f, rm1 = -1e30f;
        #pragma unroll
        for (int j = 0; j < 8; ++j) {
            rm0 = fmaxf(rm0, fmaxf(sc[j][0], sc[j][1]));
            rm1 = fmaxf(rm1, fmaxf(sc[j][2], sc[j][3]));
        }
        rm0 = fmaxf(rm0, __shfl_xor_sync(0xffffffffu, rm0, 1));
        rm0 = fmaxf(rm0, __shfl_xor_sync(0xffffffffu, rm0, 2));
        rm1 = fmaxf(rm1, __shfl_xor_sync(0xffffffffu, rm1, 1));
        rm1 = fmaxf(rm1, __shfl_xor_sync(0xffffffffu, rm1, 2));
        const float mn0 = fmaxf(m0, rm0), mn1 = fmaxf(m1, rm1);
        const float al0 = __expf(m0 - mn0), al1 = __expf(m1 - mn1);
        float s0 = 0.f, s1 = 0.f;
        #pragma unroll
        for (int j = 0; j < 8; ++j) {
            sc[j][0] = __expf(sc[j][0] - mn0);
            sc[j][1] = __expf(sc[j][1] - mn0);
            sc[j][2] = __expf(sc[j][2] - mn1);
            sc[j][3] = __expf(sc[j][3] - mn1);
            s0 += sc[j][0] + sc[j][1];
            s1 += sc[j][2] + sc[j][3];
        }
        s0 += __shfl_xor_sync(0xffffffffu, s0, 1);
        s0 += __shfl_xor_sync(0xffffffffu, s0, 2);
        s1 += __shfl_xor_sync(0xffffffffu, s1, 1);
        s1 += __shfl_xor_sync(0xffffffffu, s1, 2);
        l0 = l0 * al0 + s0;  m0 = mn0;
        l1 = l1 * al1 + s1;  m1 = mn1;
        #pragma unroll
        for (int j = 0; j < 8; ++j) {
            o[j][0] *= al0; o[j][1] *= al0;
            o[j][2] *= al1; o[j][3] *= al1;
        }

        // write P (tf32) to per-warp smem strip (rows wid*16..wid*16+15)
        #pragma unroll
        for (int j = 0; j < 8; ++j) {
            uint2 p0 = { f2tf(sc[j][0]), f2tf(sc[j][1]) };
            uint2 p1 = { f2tf(sc[j][2]), f2tf(sc[j][3]) };
            *(uint2*)&Ps[(wid*16 + g    )*APAD + j*8 + t*2] = p0;
            *(uint2*)&Ps[(wid*16 + g + 8)*APAD + j*8 + t*2] = p1;
        }
        __syncwarp();

        // O += P @ V
        #pragma unroll
        for (int ks = 0; ks < 8; ++ks) {
            uint32_t pa[4];
            pa[0] = Ps[(wid*16 + g    )*APAD + ks*8 + t    ];
            pa[1] = Ps[(wid*16 + g + 8)*APAD + ks*8 + t    ];
            pa[2] = Ps[(wid*16 + g    )*APAD + ks*8 + t + 4];
            pa[3] = Ps[(wid*16 + g + 8)*APAD + ks*8 + t + 4];
            #pragma unroll
            for (int j = 0; j < 8; ++j) {
                uint32_t b0 = Vs[(ks*8 + t    )*APAD + j*8 + g];
                uint32_t b1 = Vs[(ks*8 + t + 4)*APAD + j*8 + g];
                mma_tf32(o[j], pa, b0, b1);
            }
        }
        __syncwarp();
    }

    const float i0 = 1.f / l0, i1 = 1.f / l1;
    float* Ob = O + ((size_t)(b*Sn + qt*64 + wid*16))*Dn + h*DHn;
    #pragma unroll
    for (int j = 0; j < 8; ++j) {
        float2 v0 = { o[j][0] * i0, o[j][1] * i0 };
        float2 v1 = { o[j][2] * i1, o[j][3] * i1 };
        *(float2*)&Ob[(size_t)(g    )*Dn + j*8 + t*2] = v0;
        *(float2*)&Ob[(size_t)(g + 8)*Dn + j*8 + t*2] = v1;
    }
}

// ==================== launch ====================
extern "C" void kernel_launch(void* const* d_in, const int* in_sizes, int n_in,
                              void* d_out, int out_size) {
    const float* x     = (const float*)d_in[0];
    const int*   amask = (const int*)  d_in[1];
    const float* Wq    = (const float*)d_in[2];
    const float* Wk    = (const float*)d_in[3];
    const float* Wv    = (const float*)d_in[4];
    const float* Wo    = (const float*)d_in[5];
    const float* W1    = (const float*)d_in[6];
    const float* W2    = (const float*)d_in[7];
    const float* gamma1= (const float*)d_in[8];
    const float* beta1 = (const float*)d_in[9];
    const float* gamma2= (const float*)d_in[10];
    const float* beta2 = (const float*)d_in[11];
    float* out = (float*)d_out;

    float *xn1, *q, *k, *v, *attn, *x1, *xn2, *hbuf, *glu;
    cudaGetSymbolAddress((void**)&xn1,  g_xn1);
    cudaGetSymbolAddress((void**)&q,    g_q);
    cudaGetSymbolAddress((void**)&k,    g_k);
    cudaGetSymbolAddress((void**)&v,    g_v);
    cudaGetSymbolAddress((void**)&attn, g_attn);
    cudaGetSymbolAddress((void**)&x1,   g_x1);
    cudaGetSymbolAddress((void**)&xn2,  g_xn2);
    cudaGetSymbolAddress((void**)&hbuf, g_h);
    cudaGetSymbolAddress((void**)&glu,  g_glu);

    cudaFuncSetAttribute(attn_tf32, cudaFuncAttributeMaxDynamicSharedMemorySize, ATTN_SMEM);

    // 1. LN1
    ln_kernel<<<Mn, 256>>>(x, gamma1, beta1, xn1);

    // 2. Q,K,V projections (tf32 tensor cores)
    dim3 gD(Dn/BN, Mn/BM);
    gemm_tf32<false><<<gD, 256>>>(xn1, Wq, nullptr, q, Mn, Dn, Dn);
    gemm_tf32<false><<<gD, 256>>>(xn1, Wk, nullptr, k, Mn, Dn, Dn);
    gemm_tf32<false><<<gD, 256>>>(xn1, Wv, nullptr, v, Mn, Dn, Dn);

    // 3. causal attention (tf32 tensor cores)
    dim3 gA(Sn/64, Hn, Bn);
    attn_tf32<<<gA, 128, ATTN_SMEM>>>(q, k, v, amask, attn);

    // 4. output projection + residual
    gemm_tf32<true><<<gD, 256>>>(attn, Wo, x, x1, Mn, Dn, Dn);

    // 5. LN2
    ln_kernel<<<Mn, 256>>>(x1, gamma2, beta2, xn2);

    // 6. W1 (N=4096)
    dim3 gF(DFF/BN, Mn/BM);
    gemm_tf32<false><<<gF, 256>>>(xn2, W1, nullptr, hbuf, Mn, DFF, Dn);

    // 7. GLU
    glu_kernel<<<(Mn*DG/4)/256, 256>>>(hbuf, glu);

    // 8. W2 + residual -> out
    gemm_tf32<true><<<gD, 256>>>(glu, W2, x1, out, Mn, Dn, DG);
}

// round 4
// speedup vs baseline: 12.0740x; 1.4144x over previous
#include <cuda_runtime.h>
#include <cuda_bf16.h>
#include <math.h>
#include <stdint.h>

// Problem constants
#define Bn   2
#define Sn   2048
#define Dn   1024
#define Hn   16
#define DHn  64
#define Mn   (Bn*Sn)          // 4096 rows
#define DFF  (4*Dn)           // 4096
#define DG   (2*Dn)           // 2048
#define EPSV 1e-5f

// -------------------- scratch (device globals; no allocation) --------------------
__device__ float g_xn1 [Mn*Dn];
__device__ float g_q   [Mn*Dn];
__device__ float g_k   [Mn*Dn];
__device__ float g_v   [Mn*Dn];
__device__ float g_attn[Mn*Dn];
__device__ float g_x1  [Mn*Dn];
__device__ float g_xn2 [Mn*Dn];
__device__ float g_h   [Mn*DFF];
__device__ float g_glu [Mn*DG];
__device__ float g_wr  [10485760];   // rounded weights: q,k,v,o @1M each, W1 @4M, W2 @2M

#define WOFF_Q  0
#define WOFF_K  1048576
#define WOFF_V  2097152
#define WOFF_O  3145728
#define WOFF_1  4194304
#define WOFF_2  8388608

// -------------------- helpers --------------------
__device__ __forceinline__ uint32_t f2tf(float f) {
    uint32_t r;
    asm("cvt.rna.tf32.f32 %0, %1;" : "=r"(r) : "f"(f));
    return r;
}
__device__ __forceinline__ float f2tff(float f) { return __uint_as_float(f2tf(f)); }

__device__ __forceinline__ void mma_tf32(float c[4], const uint32_t a[4],
                                         uint32_t b0, uint32_t b1) {
    asm volatile(
        "mma.sync.aligned.m16n8k8.row.col.f32.tf32.tf32.f32 "
        "{%0,%1,%2,%3}, {%4,%5,%6,%7}, {%8,%9}, {%0,%1,%2,%3};"
        : "+f"(c[0]), "+f"(c[1]), "+f"(c[2]), "+f"(c[3])
        : "r"(a[0]), "r"(a[1]), "r"(a[2]), "r"(a[3]), "r"(b0), "r"(b1));
}

__device__ __forceinline__ uint32_t smem_u32(const void* p) {
    uint32_t a;
    asm("{ .reg .u64 t; cvta.to.shared.u64 t, %1; cvt.u32.u64 %0, t; }"
        : "=r"(a) : "l"(p));
    return a;
}

__device__ __forceinline__ void cp16(uint32_t dst, const void* src) {
    asm volatile("cp.async.cg.shared.global [%0], [%1], 16;" :: "r"(dst), "l"(src) : "memory");
}
__device__ __forceinline__ void cp_commit() { asm volatile("cp.async.commit_group;" ::: "memory"); }
template<int N>
__device__ __forceinline__ void cp_wait() { asm volatile("cp.async.wait_group %0;" :: "n"(N) : "memory"); }

// ==================== weight rounding (tf32-rna) ====================
__global__ __launch_bounds__(256) void roundw_kernel(const float* __restrict__ src,
                                                     float* __restrict__ dst, int n4) {
    const int i = blockIdx.x * blockDim.x + threadIdx.x;
    if (i < n4) {
        float4 v = ((const float4*)src)[i];
        v.x = f2tff(v.x); v.y = f2tff(v.y); v.z = f2tff(v.z); v.w = f2tff(v.w);
        ((float4*)dst)[i] = v;
    }
}

// ==================== LayerNorm (stores tf32-rounded: output feeds GEMM A only) ====================
__global__ __launch_bounds__(256) void ln_kernel(const float* __restrict__ x,
                                                 const float* __restrict__ gamma,
                                                 const float* __restrict__ beta,
                                                 float* __restrict__ out) {
    const int row = blockIdx.x;
    const int tid = threadIdx.x;
    const float4* xr = (const float4*)(x + (size_t)row * Dn);
    float4 v = xr[tid];
    float s  = v.x + v.y + v.z + v.w;
    float ss = v.x*v.x + v.y*v.y + v.z*v.z + v.w*v.w;
    #pragma unroll
    for (int off = 16; off > 0; off >>= 1) {
        s  += __shfl_xor_sync(0xffffffffu, s,  off);
        ss += __shfl_xor_sync(0xffffffffu, ss, off);
    }
    __shared__ float red[2][8];
    const int wid = tid >> 5, lid = tid & 31;
    if (lid == 0) { red[0][wid] = s; red[1][wid] = ss; }
    __syncthreads();
    __shared__ float smu, srstd;
    if (tid == 0) {
        float ts = 0.f, tss = 0.f;
        #pragma unroll
        for (int i = 0; i < 8; ++i) { ts += red[0][i]; tss += red[1][i]; }
        float mu  = ts * (1.0f / Dn);
        float var = tss * (1.0f / Dn) - mu * mu;
        smu = mu; srstd = rsqrtf(var + EPSV);
    }
    __syncthreads();
    const float mu = smu, rstd = srstd;
    float4 g = ((const float4*)gamma)[tid];
    float4 b = ((const float4*)beta)[tid];
    float4 o;
    o.x = f2tff(g.x * (v.x - mu) * rstd + b.x);
    o.y = f2tff(g.y * (v.y - mu) * rstd + b.y);
    o.z = f2tff(g.z * (v.z - mu) * rstd + b.z);
    o.w = f2tff(g.w * (v.w - mu) * rstd + b.w);
    ((float4*)(out + (size_t)row * Dn))[tid] = o;
}

// ==================== TF32 tensor GEMM, cp.async 4-stage: C = A @ B (+R) ====================
#define BM 128
#define BN 128
#define BK 16
#define STAGES 4
#define A_STRIDE 20     // floats/row: conflict-free frag loads (20g mod 32 distinct)
#define B_STRIDE 136    // floats/row: 136t mod 32 = 8t -> conflict-free
#define SA_BYTES (BM*A_STRIDE*4)        // 10240
#define SB_BYTES (BK*B_STRIDE*4)        // 8704
#define GT_SMEM  (STAGES*(SA_BYTES+SB_BYTES))   // 75776

template<bool RESID, bool ROUND>
__device__ __forceinline__ void gemm_body(
    const float* __restrict__ A, const float* __restrict__ Bm,
    const float* __restrict__ R, float* __restrict__ C,
    int M_, int N_, int K_)
{
    extern __shared__ char smem[];
    float* sA = (float*)smem;
    float* sB = (float*)(smem + STAGES*SA_BYTES);
    const uint32_t sA_u = smem_u32(sA), sB_u = smem_u32(sB);

    const int tid = threadIdx.x;
    const int bx = blockIdx.x, by = blockIdx.y;
    const int wid = tid >> 5, lane = tid & 31;
    const int g = lane >> 2, t = lane & 3;
    const int wm = (wid >> 2) * 64, wn = (wid & 3) * 32;

    // cp.async chunk assignment
    const int a_row0 = tid >> 2;                    // + 64 for second
    const int a_k0   = (tid & 3) << 2;
    const int b_row0 = tid >> 5;                    // + 8 for second
    const int b_n0   = (tid & 31) << 2;

    const int nt = K_ >> 4;
    int kload = 0;

    auto issue = [&](int kt, int st) {
        const uint32_t da = sA_u + st*SA_BYTES;
        const uint32_t db = sB_u + st*SB_BYTES;
        cp16(da + (a_row0     )*(A_STRIDE*4) + a_k0*4,
             &A[(size_t)(by*BM + a_row0     )*K_ + kt*BK + a_k0]);
        cp16(da + (a_row0 + 64)*(A_STRIDE*4) + a_k0*4,
             &A[(size_t)(by*BM + a_row0 + 64)*K_ + kt*BK + a_k0]);
        cp16(db + (b_row0    )*(B_STRIDE*4) + b_n0*4,
             &Bm[(size_t)(kt*BK + b_row0    )*N_ + bx*BN + b_n0]);
        cp16(db + (b_row0 + 8)*(B_STRIDE*4) + b_n0*4,
             &Bm[(size_t)(kt*BK + b_row0 + 8)*N_ + bx*BN + b_n0]);
    };

    float acc[4][4][4];
    #pragma unroll
    for (int i = 0; i < 4; ++i)
        #pragma unroll
        for (int j = 0; j < 4; ++j)
            #pragma unroll
            for (int e = 0; e < 4; ++e) acc[i][j][e] = 0.f;

    #pragma unroll
    for (int s = 0; s < STAGES-1; ++s) { issue(kload, s); cp_commit(); ++kload; }

    for (int kt = 0; kt < nt; ++kt) {
        cp_wait<STAGES-2>();
        __syncthreads();
        const uint32_t* fA = (const uint32_t*)(sA + (kt & (STAGES-1))*(BM*A_STRIDE));
        const uint32_t* fB = (const uint32_t*)(sB + (kt & (STAGES-1))*(BK*B_STRIDE));
        #pragma unroll
        for (int kk = 0; kk < 2; ++kk) {
            const int k0 = kk * 8;
            uint32_t afr[4][4], bfr[4][2];
            #pragma unroll
            for (int i = 0; i < 4; ++i) {
                afr[i][0] = fA[(wm + i*16 + g    )*A_STRIDE + k0 + t    ];
                afr[i][1] = fA[(wm + i*16 + g + 8)*A_STRIDE + k0 + t    ];
                afr[i][2] = fA[(wm + i*16 + g    )*A_STRIDE + k0 + t + 4];
                afr[i][3] = fA[(wm + i*16 + g + 8)*A_STRIDE + k0 + t + 4];
            }
            #pragma unroll
            for (int j = 0; j < 4; ++j) {
                bfr[j][0] = fB[(k0 + t    )*B_STRIDE + wn + j*8 + g];
                bfr[j][1] = fB[(k0 + t + 4)*B_STRIDE + wn + j*8 + g];
            }
            #pragma unroll
            for (int i = 0; i < 4; ++i)
                #pragma unroll
                for (int j = 0; j < 4; ++j)
                    mma_tf32(acc[i][j], afr[i], bfr[j][0], bfr[j][1]);
        }
        if (kload < nt) { issue(kload, kload & (STAGES-1)); ++kload; }
        cp_commit();
    }

    // epilogue
    #pragma unroll
    for (int i = 0; i < 4; ++i) {
        const int row0 = by*BM + wm + i*16 + g;
        const int row1 = row0 + 8;
        #pragma unroll
        for (int j = 0; j < 4; ++j) {
            const int col = bx*BN + wn + j*8 + t*2;
            float2 v0 = { acc[i][j][0], acc[i][j][1] };
            float2 v1 = { acc[i][j][2], acc[i][j][3] };
            if (RESID) {
                float2 r0 = *(const float2*)&R[(size_t)row0*N_ + col];
                float2 r1 = *(const float2*)&R[(size_t)row1*N_ + col];
                v0.x += r0.x; v0.y += r0.y;
                v1.x += r1.x; v1.y += r1.y;
            }
            if (ROUND) {
                v0.x = f2tff(v0.x); v0.y = f2tff(v0.y);
                v1.x = f2tff(v1.x); v1.y = f2tff(v1.y);
            }
            *(float2*)&C[(size_t)row0*N_ + col] = v0;
            *(float2*)&C[(size_t)row1*N_ + col] = v1;
        }
    }
}

template<bool RESID>
__global__ __launch_bounds__(256, 2) void gemm_k(
    const float* __restrict__ A, const float* __restrict__ Bm,
    const float* __restrict__ R, float* __restrict__ C,
    int M_, int N_, int K_)
{
    gemm_body<RESID, false>(A, Bm, R, C, M_, N_, K_);
}

// fused QKV: blockIdx.z selects weight/output; outputs rounded (feed attention MMAs)
__global__ __launch_bounds__(256, 2) void gemm_qkv(
    const float* __restrict__ A, const float* __restrict__ W,
    float* __restrict__ q, float* __restrict__ k, float* __restrict__ v)
{
    const int z = blockIdx.z;
    const float* Bm = W + (z == 0 ? WOFF_Q : z == 1 ? WOFF_K : WOFF_V);
    float* C = (z == 0) ? q : (z == 1) ? k : v;
    gemm_body<false, true>(A, Bm, nullptr, C, Mn, Dn, Dn);
}

// ==================== GLU (rounded: feeds W2 GEMM A) ====================
__global__ __launch_bounds__(256) void glu_kernel(const float* __restrict__ h,
                                                  float* __restrict__ g) {
    const int idx = blockIdx.x * blockDim.x + threadIdx.x;
    const int row = idx >> 9;
    const int c4  = idx & 511;
    float4 l = *(const float4*)&h[(size_t)row*DFF + c4*4];
    float4 r = *(const float4*)&h[(size_t)row*DFF + DG + c4*4];
    float4 o;
    o.x = f2tff(l.x / (1.f + expf(-r.x)));
    o.y = f2tff(l.y / (1.f + expf(-r.y)));
    o.z = f2tff(l.z / (1.f + expf(-r.z)));
    o.w = f2tff(l.w / (1.f + expf(-r.w)));
    *(float4*)&g[(size_t)row*DG + c4*4] = o;
}

// ==================== causal flash attention (tf32 HMMA + cp.async K/V) ====================
#define APAD 68
#define ATTN_SMEM (3 * 64 * APAD * 4)

__global__ __launch_bounds__(128) void attn_tf32(
    const float* __restrict__ Q, const float* __restrict__ K,
    const float* __restrict__ V, const int* __restrict__ mask,
    float* __restrict__ O) {
    extern __shared__ uint32_t sm_u[];
    uint32_t* Ks = sm_u;
    uint32_t* Vs = sm_u + 64*APAD;
    uint32_t* Ps = sm_u + 2*64*APAD;
    __shared__ int msk[64];
    const uint32_t ks_u = smem_u32(Ks), vs_u = smem_u32(Vs);

    const int qt = blockIdx.x, h = blockIdx.y, b = blockIdx.z;
    const int tid = threadIdx.x;
    const int wid = tid >> 5, lane = tid & 31;
    const int g = lane >> 2, t = lane & 3;

    // Q fragments (values already tf32-rounded by QKV epilogue)
    const float* Qb = Q + ((size_t)(b*Sn + qt*64 + wid*16))*Dn + h*DHn;
    uint32_t qa[8][4];
    #pragma unroll
    for (int ks = 0; ks < 8; ++ks) {
        qa[ks][0] = __float_as_uint(Qb[(size_t)(g    )*Dn + ks*8 + t    ]);
        qa[ks][1] = __float_as_uint(Qb[(size_t)(g + 8)*Dn + ks*8 + t    ]);
        qa[ks][2] = __float_as_uint(Qb[(size_t)(g    )*Dn + ks*8 + t + 4]);
        qa[ks][3] = __float_as_uint(Qb[(size_t)(g + 8)*Dn + ks*8 + t + 4]);
    }

    float o[8][4];
    #pragma unroll
    for (int j = 0; j < 8; ++j)
        #pragma unroll
        for (int e = 0; e < 4; ++e) o[j][e] = 0.f;
    float m0 = -1e30f, m1 = -1e30f, l0 = 0.f, l1 = 0.f;
    const float scale = 0.125f;

    const int rowg0 = qt*64 + wid*16 + g;
    const int rowg1 = rowg0 + 8;

    for (int kt = 0; kt <= qt; ++kt) {
        __syncthreads();
        {
            const float* Kb = K + (size_t)(b*Sn + kt*64)*Dn + h*DHn;
            const float* Vb = V + (size_t)(b*Sn + kt*64)*Dn + h*DHn;
            #pragma unroll
            for (int c = 0; c < 8; ++c) {
                const int idx = tid + c*128;
                const int rr = idx >> 4, q4 = idx & 15;
                cp16(ks_u + rr*(APAD*4) + q4*16, Kb + (size_t)rr*Dn + q4*4);
                cp16(vs_u + rr*(APAD*4) + q4*16, Vb + (size_t)rr*Dn + q4*4);
            }
            cp_commit();
        }
        if (tid < 64) msk[tid] = mask[b*Sn + kt*64 + tid];
        cp_wait<0>();
        __syncthreads();

        // S = Q @ K^T
        float sc[8][4];
        #pragma unroll
        for (int j = 0; j < 8; ++j)
            #pragma unroll
            for (int e = 0; e < 4; ++e) sc[j][e] = 0.f;
        #pragma unroll
        for (int ks = 0; ks < 8; ++ks) {
            #pragma unroll
            for (int j = 0; j < 8; ++j) {
                uint32_t b0 = Ks[(j*8 + g)*APAD + ks*8 + t    ];
                uint32_t b1 = Ks[(j*8 + g)*APAD + ks*8 + t + 4];
                mma_tf32(sc[j], qa[ks], b0, b1);
            }
        }

        #pragma unroll
        for (int j = 0; j < 8; ++j) {
            #pragma unroll
            for (int e = 0; e < 4; ++e) {
                const int cl  = j*8 + t*2 + (e & 1);
                const int kg  = kt*64 + cl;
                const int row = (e < 2) ? rowg0 : rowg1;
                const bool ok = (kg <= row) && (msk[cl] != 0);
                sc[j][e] = ok ? sc[j][e] * scale : -1e30f;
            }
        }

        float rm0 = -1e30f, rm1 = -1e30f;
        #pragma unroll
        for (int j = 0; j < 8; ++j) {
            rm0 = fmaxf(rm0, fmaxf(sc[j][0], sc[j][1]));
            rm1 = fmaxf(rm1, fmaxf(sc[j][2], sc[j][3]));
        }
        rm0 = fmaxf(rm0, __shfl_xor_sync(0xffffffffu, rm0, 1));
        rm0 = fmaxf(rm0, __shfl_xor_sync(0xffffffffu, rm0, 2));
        rm1 = fmaxf(rm1, __shfl_xor_sync(0xffffffffu, rm1, 1));
        rm1 = fmaxf(rm1, __shfl_xor_sync(0xffffffffu, rm1, 2));
        const float mn0 = fmaxf(m0, rm0), mn1 = fmaxf(m1, rm1);
        const float al0 = __expf(m0 - mn0), al1 = __expf(m1 - mn1);
        float s0 = 0.f, s1 = 0.f;
        #pragma unroll
        for (int j = 0; j < 8; ++j) {
            sc[j][0] = __expf(sc[j][0] - mn0);
            sc[j][1] = __expf(sc[j][1] - mn0);
            sc[j][2] = __expf(sc[j][2] - mn1);
            sc[j][3] = __expf(sc[j][3] - mn1);
            s0 += sc[j][0] + sc[j][1];
            s1 += sc[j][2] + sc[j][3];
        }
        s0 += __shfl_xor_sync(0xffffffffu, s0, 1);
        s0 += __shfl_xor_sync(0xffffffffu, s0, 2);
        s1 += __shfl_xor_sync(0xffffffffu, s1, 1);
        s1 += __shfl_xor_sync(0xffffffffu, s1, 2);
        l0 = l0 * al0 + s0;  m0 = mn0;
        l1 = l1 * al1 + s1;  m1 = mn1;
        #pragma unroll
        for (int j = 0; j < 8; ++j) {
            o[j][0] *= al0; o[j][1] *= al0;
            o[j][2] *= al1; o[j][3] *= al1;
        }

        // write P (tf32-rounded) to per-warp smem strip
        #pragma unroll
        for (int j = 0; j < 8; ++j) {
            uint2 p0 = { f2tf(sc[j][0]), f2tf(sc[j][1]) };
            uint2 p1 = { f2tf(sc[j][2]), f2tf(sc[j][3]) };
            *(uint2*)&Ps[(wid*16 + g    )*APAD + j*8 + t*2] = p0;
            *(uint2*)&Ps[(wid*16 + g + 8)*APAD + j*8 + t*2] = p1;
        }
        __syncwarp();

        // O += P @ V
        #pragma unroll
        for (int ks = 0; ks < 8; ++ks) {
            uint32_t pa[4];
            pa[0] = Ps[(wid*16 + g    )*APAD + ks*8 + t    ];
            pa[1] = Ps[(wid*16 + g + 8)*APAD + ks*8 + t    ];
            pa[2] = Ps[(wid*16 + g    )*APAD + ks*8 + t + 4];
            pa[3] = Ps[(wid*16 + g + 8)*APAD + ks*8 + t + 4];
            #pragma unroll
            for (int j = 0; j < 8; ++j) {
                uint32_t b0 = Vs[(ks*8 + t    )*APAD + j*8 + g];
                uint32_t b1 = Vs[(ks*8 + t + 4)*APAD + j*8 + g];
                mma_tf32(o[j], pa, b0, b1);
            }
        }
        __syncwarp();
    }

    // rounded store: attn output feeds Wo GEMM A operand only
    const float i0 = 1.f / l0, i1 = 1.f / l1;
    float* Ob = O + ((size_t)(b*Sn + qt*64 + wid*16))*Dn + h*DHn;
    #pragma unroll
    for (int j = 0; j < 8; ++j) {
        float2 v0 = { f2tff(o[j][0] * i0), f2tff(o[j][1] * i0) };
        float2 v1 = { f2tff(o[j][2] * i1), f2tff(o[j][3] * i1) };
        *(float2*)&Ob[(size_t)(g    )*Dn + j*8 + t*2] = v0;
        *(float2*)&Ob[(size_t)(g + 8)*Dn + j*8 + t*2] = v1;
    }
}

// ==================== launch ====================
extern "C" void kernel_launch(void* const* d_in, const int* in_sizes, int n_in,
                              void* d_out, int out_size) {
    const float* x     = (const float*)d_in[0];
    const int*   amask = (const int*)  d_in[1];
    const float* Wq    = (const float*)d_in[2];
    const float* Wk    = (const float*)d_in[3];
    const float* Wv    = (const float*)d_in[4];
    const float* Wo    = (const float*)d_in[5];
    const float* W1    = (const float*)d_in[6];
    const float* W2    = (const float*)d_in[7];
    const float* gamma1= (const float*)d_in[8];
    const float* beta1 = (const float*)d_in[9];
    const float* gamma2= (const float*)d_in[10];
    const float* beta2 = (const float*)d_in[11];
    float* out = (float*)d_out;

    float *xn1, *q, *k, *v, *attn, *x1, *xn2, *hbuf, *glu, *wr;
    cudaGetSymbolAddress((void**)&xn1,  g_xn1);
    cudaGetSymbolAddress((void**)&q,    g_q);
    cudaGetSymbolAddress((void**)&k,    g_k);
    cudaGetSymbolAddress((void**)&v,    g_v);
    cudaGetSymbolAddress((void**)&attn, g_attn);
    cudaGetSymbolAddress((void**)&x1,   g_x1);
    cudaGetSymbolAddress((void**)&xn2,  g_xn2);
    cudaGetSymbolAddress((void**)&hbuf, g_h);
    cudaGetSymbolAddress((void**)&glu,  g_glu);
    cudaGetSymbolAddress((void**)&wr,   g_wr);

    cudaFuncSetAttribute(attn_tf32, cudaFuncAttributeMaxDynamicSharedMemorySize, ATTN_SMEM);
    cudaFuncSetAttribute(gemm_qkv,      cudaFuncAttributeMaxDynamicSharedMemorySize, GT_SMEM);
    cudaFuncSetAttribute(gemm_k<false>, cudaFuncAttributeMaxDynamicSharedMemorySize, GT_SMEM);
    cudaFuncSetAttribute(gemm_k<true>,  cudaFuncAttributeMaxDynamicSharedMemorySize, GT_SMEM);

    // 0. round weights to tf32 once per call
    roundw_kernel<<<(1048576/4+255)/256, 256>>>(Wq, wr + WOFF_Q, 1048576/4);
    roundw_kernel<<<(1048576/4+255)/256, 256>>>(Wk, wr + WOFF_K, 1048576/4);
    roundw_kernel<<<(1048576/4+255)/256, 256>>>(Wv, wr + WOFF_V, 1048576/4);
    roundw_kernel<<<(1048576/4+255)/256, 256>>>(Wo, wr + WOFF_O, 1048576/4);
    roundw_kernel<<<(4194304/4+255)/256, 256>>>(W1, wr + WOFF_1, 4194304/4);
    roundw_kernel<<<(2097152/4+255)/256, 256>>>(W2, wr + WOFF_2, 2097152/4);

    // 1. LN1 (rounded output)
    ln_kernel<<<Mn, 256>>>(x, gamma1, beta1, xn1);

    // 2. fused Q,K,V projections
    dim3 gQKV(Dn/BN, Mn/BM, 3);
    gemm_qkv<<<gQKV, 256, GT_SMEM>>>(xn1, wr, q, k, v);

    // 3. causal attention
    dim3 gA(Sn/64, Hn, Bn);
    attn_tf32<<<gA, 128, ATTN_SMEM>>>(q, k, v, amask, attn);

    // 4. output projection + residual (exact fp32 residual)
    dim3 gD(Dn/BN, Mn/BM);
    gemm_k<true><<<gD, 256, GT_SMEM>>>(attn, wr + WOFF_O, x, x1, Mn, Dn, Dn);

    // 5. LN2 (rounded output)
    ln_kernel<<<Mn, 256>>>(x1, gamma2, beta2, xn2);

    // 6. W1 (N=4096)
    dim3 gF(DFF/BN, Mn/BM);
    gemm_k<false><<<gF, 256, GT_SMEM>>>(xn2, wr + WOFF_1, nullptr, hbuf, Mn, DFF, Dn);

    // 7. GLU (rounded output)
    glu_kernel<<<(Mn*DG/4)/256, 256>>>(hbuf, glu);

    // 8. W2 + residual -> out
    gemm_k<true><<<gD, 256, GT_SMEM>>>(glu, wr + WOFF_2, x1, out, Mn, Dn, DG);
}